// round 9
// baseline (speedup 1.0000x reference)
#include <cuda_runtime.h>
#include <cuda_fp16.h>
#include <stdint.h>

#define DIM 768
#define NHEAD 12
#define HD 64
#define BATCH 8
#define SEQ 1024
#define TOKENS (BATCH*SEQ)   // 8192
#define QKV_N (3*DIM)        // 2304

// log2e * headdim^-0.5 folded into q at QKV epilogue -> S is in log2 units.
#define QS   (0.125f * 1.4426950408889634f)
#define ONESH2 0x3C003C00u   // half2(1.0, 1.0)

// Scratch (no allocation allowed)
__device__ __half g_xH  [TOKENS * DIM];
__device__ __half g_wqH [QKV_N * DIM];
__device__ __half g_wpH [DIM * DIM];
__device__ __half g_qkvH[TOKENS * QKV_N];
__device__ __half g_attnH[TOKENS * DIM];

__device__ __forceinline__ uint32_t smem_u32(const void* p) {
    return (uint32_t)__cvta_generic_to_shared(p);
}
__device__ __forceinline__ uint32_t packh2(float x, float y) {
    __half2 h = __floats2half2_rn(x, y);
    return *reinterpret_cast<uint32_t*>(&h);
}
__device__ __forceinline__ uint32_t ex2x2(uint32_t x) {
    uint32_t r;
    asm("ex2.approx.f16x2 %0, %1;\n" : "=r"(r) : "r"(x));
    return r;
}
__device__ __forceinline__ void ldsm4(uint32_t& r0, uint32_t& r1, uint32_t& r2,
                                      uint32_t& r3, uint32_t a) {
    asm volatile("ldmatrix.sync.aligned.m8n8.x4.shared.b16 {%0,%1,%2,%3},[%4];"
                 : "=r"(r0), "=r"(r1), "=r"(r2), "=r"(r3) : "r"(a));
}
__device__ __forceinline__ void ldsm4t(uint32_t& r0, uint32_t& r1, uint32_t& r2,
                                       uint32_t& r3, uint32_t a) {
    asm volatile("ldmatrix.sync.aligned.m8n8.x4.trans.shared.b16 {%0,%1,%2,%3},[%4];"
                 : "=r"(r0), "=r"(r1), "=r"(r2), "=r"(r3) : "r"(a));
}
__device__ __forceinline__ void mma16816(float c[4],
    uint32_t a0, uint32_t a1, uint32_t a2, uint32_t a3, uint32_t b0, uint32_t b1)
{
    asm volatile(
        "mma.sync.aligned.m16n8k16.row.col.f32.f16.f16.f32 "
        "{%0,%1,%2,%3},{%4,%5,%6,%7},{%8,%9},{%0,%1,%2,%3};"
        : "+f"(c[0]), "+f"(c[1]), "+f"(c[2]), "+f"(c[3])
        : "r"(a0), "r"(a1), "r"(a2), "r"(a3), "r"(b0), "r"(b1));
}
__device__ __forceinline__ void cp16(uint32_t dst, const void* src) {
    asm volatile("cp.async.cg.shared.global [%0], [%1], 16;\n" :: "r"(dst), "l"(src));
}
__device__ __forceinline__ void cp_commit() {
    asm volatile("cp.async.commit_group;\n" ::: "memory");
}
template<int N> __device__ __forceinline__ void cp_wait() {
    asm volatile("cp.async.wait_group %0;\n" :: "n"(N) : "memory");
}

// ---------------------------------------------------------------------------
// fused fp32 -> fp16 conversion of x, qkv_w, proj_w in one launch
// ---------------------------------------------------------------------------
#define CV1 (TOKENS * DIM / 8)
#define CV2 (CV1 + QKV_N * DIM / 8)
#define CV3 (CV2 + DIM * DIM / 8)
__global__ __launch_bounds__(256) void cvt_all(
    const float* __restrict__ x, const float* __restrict__ wq,
    const float* __restrict__ wp, __half* __restrict__ xH,
    __half* __restrict__ wqH, __half* __restrict__ wpH)
{
    int i = blockIdx.x * 256 + threadIdx.x;
    const float* in;
    __half* out;
    int j;
    if (i < CV1)      { in = x;  out = xH;  j = i; }
    else if (i < CV2) { in = wq; out = wqH; j = i - CV1; }
    else if (i < CV3) { in = wp; out = wpH; j = i - CV2; }
    else return;
    float4 a = ((const float4*)in)[2 * j];
    float4 b = ((const float4*)in)[2 * j + 1];
    uint4 o;
    o.x = packh2(a.x, a.y); o.y = packh2(a.z, a.w);
    o.z = packh2(b.x, b.y); o.w = packh2(b.z, b.w);
    ((uint4*)out)[j] = o;
}

// ---------------------------------------------------------------------------
// fp16 GEMM, mma.m16n8k16: C[m][n] = sum_k A[m][k]*W[n][k] + bias[n]
// 64x128 block, 4 warps (2x2 of 32x64 warp tiles), BK=32, 3-stage cp.async,
// 3 CTAs/SM. One __syncthreads per chunk (prefetch targets stage (c+2)%3
// == (c-1)%3, whose compute finished before this iteration's barrier).
// LNQK: fuse per-head(64) LayerNorm for n<1536 (q,k); q scaled by QS.
// ---------------------------------------------------------------------------
#define GSTG3 12288   // stage bytes: A 64x64B (4KB) + B 128x64B (8KB)
template<bool HALF_OUT, bool LNQK>
__global__ __launch_bounds__(128, 3) void hgemm3(
    const __half* __restrict__ A, const __half* __restrict__ W,
    const float* __restrict__ bias, void* __restrict__ Cout,
    const float* __restrict__ gamma, const float* __restrict__ beta,
    int M, int N, int K)
{
    __shared__ __align__(16) unsigned char sm[3 * GSTG3];

    const int bm = blockIdx.y * 64, bn = blockIdx.x * 128;
    const int t = threadIdx.x, lane = t & 31, warp = t >> 5;
    const int wm = (warp & 1) * 32, wn = (warp >> 1) * 64;
    const int g = lane >> 2, tg = lane & 3;
    const int ra = (lane & 7) + 8 * ((lane >> 3) & 1), ca = lane >> 4;
    const int rb = (lane & 7) + 8 * (lane >> 4),       cb = (lane >> 3) & 1;
    const uint32_t sbase = smem_u32(sm);

    // load slots: A 256 chunks (2/thread), B 512 chunks (4/thread)
    uint32_t aswo[2], wswo[4];
    const __half* ag[2];
    const __half* wg[4];
#pragma unroll
    for (int l = 0; l < 2; l++) {
        int s = t + l * 128, r = s >> 2, c = s & 3;
        aswo[l] = (uint32_t)(r * 64 + ((c ^ ((r >> 1) & 3)) * 16));
        ag[l] = A + (size_t)(bm + r) * K + c * 8;
    }
#pragma unroll
    for (int l = 0; l < 4; l++) {
        int s = t + l * 128, r = s >> 2, c = s & 3;
        wswo[l] = (uint32_t)(4096 + r * 64 + ((c ^ ((r >> 1) & 3)) * 16));
        wg[l] = W + (size_t)(bn + r) * K + c * 8;
    }

    const int nchunk = K >> 5;
#pragma unroll
    for (int c = 0; c < 2; c++) {
        uint32_t ab = sbase + c * GSTG3;
#pragma unroll
        for (int l = 0; l < 2; l++) cp16(ab + aswo[l], ag[l] + c * 32);
#pragma unroll
        for (int l = 0; l < 4; l++) cp16(ab + wswo[l], wg[l] + c * 32);
        cp_commit();
    }

    float acc[2][8][4];
#pragma unroll
    for (int i = 0; i < 2; i++)
#pragma unroll
        for (int j = 0; j < 8; j++)
#pragma unroll
            for (int c = 0; c < 4; c++) acc[i][j][c] = 0.f;

    for (int c = 0; c < nchunk; c++) {
        cp_wait<1>();
        __syncthreads();
        const uint32_t ab = sbase + (c % 3) * GSTG3;
#pragma unroll
        for (int h = 0; h < 2; h++) {
            uint32_t a[2][4], bf[8][2];
#pragma unroll
            for (int im = 0; im < 2; im++) {
                int m = wm + 16 * im + ra;
                ldsm4(a[im][0], a[im][1], a[im][2], a[im][3],
                      ab + m * 64 + (((2 * h + ca) ^ ((m >> 1) & 3)) * 16));
            }
#pragma unroll
            for (int u = 0; u < 4; u++) {
                int n = wn + 16 * u + rb;
                ldsm4(bf[2 * u][0], bf[2 * u][1], bf[2 * u + 1][0], bf[2 * u + 1][1],
                      ab + 4096 + n * 64 + (((2 * h + cb) ^ ((n >> 1) & 3)) * 16));
            }
#pragma unroll
            for (int im = 0; im < 2; im++)
#pragma unroll
                for (int jn = 0; jn < 8; jn++)
                    mma16816(acc[im][jn], a[im][0], a[im][1], a[im][2], a[im][3],
                             bf[jn][0], bf[jn][1]);
        }
        int pf = c + 2;
        if (pf < nchunk) {
            uint32_t ab2 = sbase + (pf % 3) * GSTG3;
#pragma unroll
            for (int l = 0; l < 2; l++) cp16(ab2 + aswo[l], ag[l] + pf * 32);
#pragma unroll
            for (int l = 0; l < 4; l++) cp16(ab2 + wswo[l], wg[l] + pf * 32);
        }
        cp_commit();
    }

    const bool do_ln = LNQK && (bn + wn) < 2 * DIM;   // q or k region
    const float fin = (LNQK && (bn + wn) < DIM) ? QS : 1.f;

#pragma unroll
    for (int im = 0; im < 2; im++) {
        int r0 = bm + wm + 16 * im + g;
#pragma unroll
        for (int jn = 0; jn < 8; jn++) {
            int c0 = bn + wn + 8 * jn + 2 * tg;
            float bx = bias[c0], by = bias[c0 + 1];
            acc[im][jn][0] += bx; acc[im][jn][1] += by;
            acc[im][jn][2] += bx; acc[im][jn][3] += by;
        }
        if (do_ln) {
            float s0 = 0.f, ss0 = 0.f, s1 = 0.f, ss1 = 0.f;
#pragma unroll
            for (int jn = 0; jn < 8; jn++) {
                float v0 = acc[im][jn][0], v1 = acc[im][jn][1];
                float v2 = acc[im][jn][2], v3 = acc[im][jn][3];
                s0 += v0 + v1; ss0 += v0 * v0 + v1 * v1;
                s1 += v2 + v3; ss1 += v2 * v2 + v3 * v3;
            }
            s0  += __shfl_xor_sync(0xffffffffu, s0, 1);
            s0  += __shfl_xor_sync(0xffffffffu, s0, 2);
            ss0 += __shfl_xor_sync(0xffffffffu, ss0, 1);
            ss0 += __shfl_xor_sync(0xffffffffu, ss0, 2);
            s1  += __shfl_xor_sync(0xffffffffu, s1, 1);
            s1  += __shfl_xor_sync(0xffffffffu, s1, 2);
            ss1 += __shfl_xor_sync(0xffffffffu, ss1, 1);
            ss1 += __shfl_xor_sync(0xffffffffu, ss1, 2);
            float mu0 = s0 * (1.f / 64.f);
            float mu1 = s1 * (1.f / 64.f);
            float rs0 = rsqrtf(ss0 * (1.f / 64.f) - mu0 * mu0 + 1e-5f);
            float rs1 = rsqrtf(ss1 * (1.f / 64.f) - mu1 * mu1 + 1e-5f);
#pragma unroll
            for (int jn = 0; jn < 8; jn++) {
                int cs = 8 * jn + 2 * tg;
                float ga = gamma[cs], gb = gamma[cs + 1];
                float ba = beta[cs],  bb = beta[cs + 1];
                acc[im][jn][0] = ((acc[im][jn][0] - mu0) * rs0 * ga + ba) * fin;
                acc[im][jn][1] = ((acc[im][jn][1] - mu0) * rs0 * gb + bb) * fin;
                acc[im][jn][2] = ((acc[im][jn][2] - mu1) * rs1 * ga + ba) * fin;
                acc[im][jn][3] = ((acc[im][jn][3] - mu1) * rs1 * gb + bb) * fin;
            }
        }
#pragma unroll
        for (int jn = 0; jn < 8; jn++) {
            int c0 = bn + wn + 8 * jn + 2 * tg;
            if (HALF_OUT) {
                __half* C = (__half*)Cout;
                *(uint32_t*)(C + (size_t)r0 * N + c0) =
                    packh2(acc[im][jn][0], acc[im][jn][1]);
                *(uint32_t*)(C + (size_t)(r0 + 8) * N + c0) =
                    packh2(acc[im][jn][2], acc[im][jn][3]);
            } else {
                float* C = (float*)Cout;
                *(float2*)(C + (size_t)r0 * N + c0) =
                    make_float2(acc[im][jn][0], acc[im][jn][1]);
                *(float2*)(C + (size_t)(r0 + 8) * N + c0) =
                    make_float2(acc[im][jn][2], acc[im][jn][3]);
            }
        }
    }
}

// ---------------------------------------------------------------------------
// Flash attention, unnormalized softmax (P = 2^S; LN bounds |S|<=11.6 so
// 2^S fits fp16; normalization cancels the missing max-shift).
// BM=128 (4 warps x 32 rows), BN=64, hd=64. Triple-buffered K/V cp.async,
// ONE __syncthreads per iteration. Row sums via all-ones MMA.
// ---------------------------------------------------------------------------
__global__ __launch_bounds__(128, 2) void attn3(
    const __half* __restrict__ qkv, __half* __restrict__ out)
{
    __shared__ __align__(16) unsigned char sm[3 * 16384];   // 48KB

    const int q0 = blockIdx.x * 128;
    const int bh = blockIdx.y;
    const int b = bh / NHEAD, h = bh % NHEAD;
    const int t = threadIdx.x, lane = t & 31, warp = t >> 5;
    const int g = lane >> 2, tg = lane & 3;
    const int ra = (lane & 7) + 8 * ((lane >> 3) & 1), ca = lane >> 4;
    const int rb = (lane & 7) + 8 * (lane >> 4),       cb = (lane >> 3) & 1;
    const uint32_t sbase = smem_u32(sm);

    const __half* kvg = qkv + ((size_t)b * SEQ) * QKV_N + DIM + h * HD;
    int lrow[4], lch[4];
    uint32_t loff[4];
#pragma unroll
    for (int l = 0; l < 4; l++) {
        int s = t + l * 128;
        lrow[l] = s >> 3; lch[l] = s & 7;
        loff[l] = (uint32_t)(lrow[l] * 128 + ((lch[l] ^ (lrow[l] & 7)) * 16));
    }

    // ---- Stage Q into buf2; prefetch KV0 into buf0 concurrently ----
    {
        const __half* qg = qkv + ((size_t)(b * SEQ + q0)) * QKV_N + h * HD;
        uint32_t qb = sbase + 2 * 16384;
#pragma unroll
        for (int l = 0; l < 8; l++) {
            int s = t + l * 128, r = s >> 3, ch = s & 7;
            cp16(qb + r * 128 + ((ch ^ (r & 7)) * 16),
                 qg + (size_t)r * QKV_N + ch * 8);
        }
        cp_commit();
#pragma unroll
        for (int l = 0; l < 4; l++) {
            const __half* kg = kvg + (size_t)lrow[l] * QKV_N + lch[l] * 8;
            cp16(sbase + loff[l], kg);
            cp16(sbase + 8192 + loff[l], kg + DIM);
        }
        cp_commit();
        cp_wait<1>();   // Q ready (KV0 may still be in flight)
        __syncthreads();
    }
    uint32_t Qa[2][4][4];
    {
        uint32_t qb = sbase + 2 * 16384;
#pragma unroll
        for (int mi = 0; mi < 2; mi++) {
            int m = warp * 32 + mi * 16 + ra;
#pragma unroll
            for (int kd = 0; kd < 4; kd++)
                ldsm4(Qa[mi][kd][0], Qa[mi][kd][1], Qa[mi][kd][2], Qa[mi][kd][3],
                      qb + m * 128 + (((2 * kd + ca) ^ (m & 7)) * 16));
        }
    }
    __syncthreads();   // buf2 free for KV reuse

    float Oacc[2][8][4];
#pragma unroll
    for (int mi = 0; mi < 2; mi++)
#pragma unroll
        for (int dn = 0; dn < 8; dn++)
#pragma unroll
            for (int c = 0; c < 4; c++) Oacc[mi][dn][c] = 0.f;
    float Lacc[2][4];
#pragma unroll
    for (int mi = 0; mi < 2; mi++)
#pragma unroll
        for (int c = 0; c < 4; c++) Lacc[mi][c] = 0.f;

    const int NIT = SEQ / 64;   // 16
    for (int it = 0; it < NIT; it++) {
        if (it + 1 < NIT) {
            uint32_t bb = sbase + ((it + 1) % 3) * 16384;
            const __half* kg0 = kvg + (size_t)(it + 1) * 64 * QKV_N;
#pragma unroll
            for (int l = 0; l < 4; l++) {
                const __half* kg = kg0 + (size_t)lrow[l] * QKV_N + lch[l] * 8;
                cp16(bb + loff[l], kg);
                cp16(bb + 8192 + loff[l], kg + DIM);
            }
        }
        cp_commit();
        cp_wait<1>();
        __syncthreads();
        const uint32_t kb = sbase + (it % 3) * 16384;
        const uint32_t vb = kb + 8192;

        // S = Q @ K^T (log2 units; QS folded into q)
        float S[2][8][4];
#pragma unroll
        for (int mi = 0; mi < 2; mi++)
#pragma unroll
            for (int jn = 0; jn < 8; jn++)
#pragma unroll
                for (int c = 0; c < 4; c++) S[mi][jn][c] = 0.f;
#pragma unroll
        for (int kd = 0; kd < 4; kd++) {
#pragma unroll
            for (int u = 0; u < 4; u++) {
                int n = 16 * u + rb;
                uint32_t b0a, b1a, b0b, b1b;
                ldsm4(b0a, b1a, b0b, b1b,
                      kb + n * 128 + (((2 * kd + cb) ^ (n & 7)) * 16));
#pragma unroll
                for (int mi = 0; mi < 2; mi++) {
                    mma16816(S[mi][2 * u],     Qa[mi][kd][0], Qa[mi][kd][1],
                             Qa[mi][kd][2], Qa[mi][kd][3], b0a, b1a);
                    mma16816(S[mi][2 * u + 1], Qa[mi][kd][0], Qa[mi][kd][1],
                             Qa[mi][kd][2], Qa[mi][kd][3], b0b, b1b);
                }
            }
        }

        // P = 2^S in fp16 (pack, then one MUFU per 2 values)
        uint32_t Pa[2][4][4];
#pragma unroll
        for (int mi = 0; mi < 2; mi++) {
#pragma unroll
            for (int kt = 0; kt < 4; kt++) {
                Pa[mi][kt][0] = ex2x2(packh2(S[mi][2 * kt][0],     S[mi][2 * kt][1]));
                Pa[mi][kt][1] = ex2x2(packh2(S[mi][2 * kt][2],     S[mi][2 * kt][3]));
                Pa[mi][kt][2] = ex2x2(packh2(S[mi][2 * kt + 1][0], S[mi][2 * kt + 1][1]));
                Pa[mi][kt][3] = ex2x2(packh2(S[mi][2 * kt + 1][2], S[mi][2 * kt + 1][3]));
            }
#pragma unroll
            for (int kt = 0; kt < 4; kt++)
                mma16816(Lacc[mi], Pa[mi][kt][0], Pa[mi][kt][1],
                         Pa[mi][kt][2], Pa[mi][kt][3], ONESH2, ONESH2);
        }

        // O += P @ V
#pragma unroll
        for (int kt = 0; kt < 4; kt++) {
            int j = 16 * kt + ra;
#pragma unroll
            for (int dp = 0; dp < 4; dp++) {
                uint32_t b0a, b1a, b0b, b1b;
                ldsm4t(b0a, b1a, b0b, b1b,
                       vb + j * 128 + (((2 * dp + ca) ^ (j & 7)) * 16));
#pragma unroll
                for (int mi = 0; mi < 2; mi++) {
                    mma16816(Oacc[mi][2 * dp],     Pa[mi][kt][0], Pa[mi][kt][1],
                             Pa[mi][kt][2], Pa[mi][kt][3], b0a, b1a);
                    mma16816(Oacc[mi][2 * dp + 1], Pa[mi][kt][0], Pa[mi][kt][1],
                             Pa[mi][kt][2], Pa[mi][kt][3], b0b, b1b);
                }
            }
        }
    }

    // Normalize + store
#pragma unroll
    for (int mi = 0; mi < 2; mi++) {
        float inv0 = 1.f / Lacc[mi][0], inv1 = 1.f / Lacc[mi][2];
        int r0 = q0 + warp * 32 + mi * 16 + g;
        __half* o0 = out + ((size_t)b * SEQ + r0) * DIM + h * HD;
        __half* o1 = o0 + 8 * DIM;
#pragma unroll
        for (int dn = 0; dn < 8; dn++) {
            int c0 = 8 * dn + 2 * tg;
            *(uint32_t*)(o0 + c0) = packh2(Oacc[mi][dn][0] * inv0,
                                           Oacc[mi][dn][1] * inv0);
            *(uint32_t*)(o1 + c0) = packh2(Oacc[mi][dn][2] * inv1,
                                           Oacc[mi][dn][3] * inv1);
        }
    }
}

// ---------------------------------------------------------------------------
extern "C" void kernel_launch(void* const* d_in, const int* in_sizes, int n_in,
                              void* d_out, int out_size)
{
    const float* x      = (const float*)d_in[0];
    const float* qkv_w  = (const float*)d_in[1];
    const float* qkv_b  = (const float*)d_in[2];
    const float* proj_w = (const float*)d_in[3];
    const float* proj_b = (const float*)d_in[4];
    const float* qn_g   = (const float*)d_in[5];
    const float* qn_b   = (const float*)d_in[6];
    float* out = (float*)d_out;

    __half *xH, *wqH, *wpH, *qkvH, *attnH;
    cudaGetSymbolAddress((void**)&xH,    g_xH);
    cudaGetSymbolAddress((void**)&wqH,   g_wqH);
    cudaGetSymbolAddress((void**)&wpH,   g_wpH);
    cudaGetSymbolAddress((void**)&qkvH,  g_qkvH);
    cudaGetSymbolAddress((void**)&attnH, g_attnH);

    // 0) all fp32 -> fp16 conversions in one launch
    cvt_all<<<(CV3 + 255) / 256, 256>>>(x, qkv_w, proj_w, xH, wqH, wpH);

    // 1) QKV projection + fused LayerNorm(q,k) + q-scale (fp16 out)
    hgemm3<true, true><<<dim3(QKV_N / 128, TOKENS / 64), 128>>>(
        xH, wqH, qkv_b, qkvH, qn_g, qn_b, TOKENS, QKV_N, DIM);

    // 2) Attention, unnormalized-exponent softmax (fp16 out)
    attn3<<<dim3(SEQ / 128, BATCH * NHEAD), 128>>>(qkvH, attnH);

    // 3) Output projection (fp32 out)
    hgemm3<false, false><<<dim3(DIM / 128, TOKENS / 64), 128>>>(
        attnH, wpH, proj_b, out, nullptr, nullptr, TOKENS, DIM, DIM);
}

// round 10
// speedup vs baseline: 1.0730x; 1.0730x over previous
#include <cuda_runtime.h>
#include <cuda_fp16.h>
#include <stdint.h>

#define DIM 768
#define NHEAD 12
#define HD 64
#define BATCH 8
#define SEQ 1024
#define TOKENS (BATCH*SEQ)   // 8192
#define QKV_N (3*DIM)        // 2304

// log2e * headdim^-0.5 folded into q at QKV epilogue -> S is in log2 units.
#define QS   (0.125f * 1.4426950408889634f)
#define ONESH2 0x3C003C00u   // half2(1.0, 1.0)

// Scratch (no allocation allowed)
__device__ __half g_xH  [TOKENS * DIM];
__device__ __half g_wqH [QKV_N * DIM];
__device__ __half g_wpH [DIM * DIM];
__device__ __half g_qkvH[TOKENS * QKV_N];
__device__ __half g_attnH[TOKENS * DIM];

__device__ __forceinline__ uint32_t smem_u32(const void* p) {
    return (uint32_t)__cvta_generic_to_shared(p);
}
__device__ __forceinline__ uint32_t packh2(float x, float y) {
    __half2 h = __floats2half2_rn(x, y);
    return *reinterpret_cast<uint32_t*>(&h);
}
__device__ __forceinline__ uint32_t ex2x2(uint32_t x) {
    uint32_t r;
    asm("ex2.approx.f16x2 %0, %1;\n" : "=r"(r) : "r"(x));
    return r;
}
__device__ __forceinline__ void ldsm4(uint32_t& r0, uint32_t& r1, uint32_t& r2,
                                      uint32_t& r3, uint32_t a) {
    asm volatile("ldmatrix.sync.aligned.m8n8.x4.shared.b16 {%0,%1,%2,%3},[%4];"
                 : "=r"(r0), "=r"(r1), "=r"(r2), "=r"(r3) : "r"(a));
}
__device__ __forceinline__ void ldsm4t(uint32_t& r0, uint32_t& r1, uint32_t& r2,
                                       uint32_t& r3, uint32_t a) {
    asm volatile("ldmatrix.sync.aligned.m8n8.x4.trans.shared.b16 {%0,%1,%2,%3},[%4];"
                 : "=r"(r0), "=r"(r1), "=r"(r2), "=r"(r3) : "r"(a));
}
__device__ __forceinline__ void mma16816(float c[4],
    uint32_t a0, uint32_t a1, uint32_t a2, uint32_t a3, uint32_t b0, uint32_t b1)
{
    asm volatile(
        "mma.sync.aligned.m16n8k16.row.col.f32.f16.f16.f32 "
        "{%0,%1,%2,%3},{%4,%5,%6,%7},{%8,%9},{%0,%1,%2,%3};"
        : "+f"(c[0]), "+f"(c[1]), "+f"(c[2]), "+f"(c[3])
        : "r"(a0), "r"(a1), "r"(a2), "r"(a3), "r"(b0), "r"(b1));
}
__device__ __forceinline__ void cp16(uint32_t dst, const void* src) {
    asm volatile("cp.async.cg.shared.global [%0], [%1], 16;\n" :: "r"(dst), "l"(src));
}
__device__ __forceinline__ void cp_commit() {
    asm volatile("cp.async.commit_group;\n" ::: "memory");
}
template<int N> __device__ __forceinline__ void cp_wait() {
    asm volatile("cp.async.wait_group %0;\n" :: "n"(N) : "memory");
}

// ---------------------------------------------------------------------------
// fused fp32 -> fp16 conversion of x, qkv_w, proj_w in one launch
// ---------------------------------------------------------------------------
#define CV1 (TOKENS * DIM / 8)
#define CV2 (CV1 + QKV_N * DIM / 8)
#define CV3 (CV2 + DIM * DIM / 8)
__global__ __launch_bounds__(256) void cvt_all(
    const float* __restrict__ x, const float* __restrict__ wq,
    const float* __restrict__ wp, __half* __restrict__ xH,
    __half* __restrict__ wqH, __half* __restrict__ wpH)
{
    int i = blockIdx.x * 256 + threadIdx.x;
    const float* in;
    __half* out;
    int j;
    if (i < CV1)      { in = x;  out = xH;  j = i; }
    else if (i < CV2) { in = wq; out = wqH; j = i - CV1; }
    else if (i < CV3) { in = wp; out = wpH; j = i - CV2; }
    else return;
    float4 a = ((const float4*)in)[2 * j];
    float4 b = ((const float4*)in)[2 * j + 1];
    uint4 o;
    o.x = packh2(a.x, a.y); o.y = packh2(a.z, a.w);
    o.z = packh2(b.x, b.y); o.w = packh2(b.z, b.w);
    ((uint4*)out)[j] = o;
}

// ---------------------------------------------------------------------------
// fp16 GEMM, mma.m16n8k16: C[m][n] = sum_k A[m][k]*W[n][k] + bias[n]
// 128x128 block, 4 warps (2x2 of 64x64 warp tiles), BK=64, 3-stage cp.async
// with DYNAMIC smem (96KB; 2 CTAs/SM = 192KB). Half the barriers of BK=32.
// smem rows of 64 halves (128B), swizzle chunk ^ (row&7).
// LNQK: fuse per-head(64) LayerNorm for n<1536 (q,k); q scaled by QS.
// ---------------------------------------------------------------------------
#define STG4 32768   // stage bytes: A 128x128B (16KB) + B 128x128B (16KB)
template<bool HALF_OUT, bool LNQK>
__global__ __launch_bounds__(128, 2) void hgemm4(
    const __half* __restrict__ A, const __half* __restrict__ W,
    const float* __restrict__ bias, void* __restrict__ Cout,
    const float* __restrict__ gamma, const float* __restrict__ beta,
    int M, int N, int K)
{
    extern __shared__ __align__(16) unsigned char sm4[];

    const int bm = blockIdx.y * 128, bn = blockIdx.x * 128;
    const int t = threadIdx.x, lane = t & 31, warp = t >> 5;
    const int wm = (warp & 1) * 64, wn = (warp >> 1) * 64;
    const int g = lane >> 2, tg = lane & 3;
    const int ra = (lane & 7) + 8 * ((lane >> 3) & 1), ca = lane >> 4;
    const int rb = (lane & 7) + 8 * (lane >> 4),       cb = (lane >> 3) & 1;
    const uint32_t sbase = smem_u32(sm4);

    // load slots: A/B tiles are 128 rows x 8 chunks(16B) = 1024 chunks each;
    // 8 chunks per thread per tile. s = t + l*128 -> row = s>>3, ch = s&7.
    uint32_t swo[8];
    const __half* ag[8];
    const __half* wg[8];
#pragma unroll
    for (int l = 0; l < 8; l++) {
        int s = t + l * 128, r = s >> 3, ch = s & 7;
        swo[l] = (uint32_t)(r * 128 + ((ch ^ (r & 7)) * 16));
        ag[l] = A + (size_t)(bm + r) * K + ch * 8;
        wg[l] = W + (size_t)(bn + r) * K + ch * 8;
    }

    const int nchunk = K >> 6;   // BK = 64
#pragma unroll
    for (int c = 0; c < 2; c++) {
        uint32_t ab = sbase + c * STG4;
#pragma unroll
        for (int l = 0; l < 8; l++) cp16(ab + swo[l], ag[l] + c * 64);
#pragma unroll
        for (int l = 0; l < 8; l++) cp16(ab + 16384 + swo[l], wg[l] + c * 64);
        cp_commit();
    }

    float acc[4][8][4];
#pragma unroll
    for (int i = 0; i < 4; i++)
#pragma unroll
        for (int j = 0; j < 8; j++)
#pragma unroll
            for (int c = 0; c < 4; c++) acc[i][j][c] = 0.f;

    for (int c = 0; c < nchunk; c++) {
        cp_wait<1>();
        __syncthreads();
        const uint32_t ab = sbase + (c % 3) * STG4;
#pragma unroll
        for (int h = 0; h < 4; h++) {    // 4 k16-substeps per BK=64
            uint32_t a[4][4], bf[8][2];
#pragma unroll
            for (int im = 0; im < 4; im++) {
                int m = wm + 16 * im + ra;
                ldsm4(a[im][0], a[im][1], a[im][2], a[im][3],
                      ab + m * 128 + (((2 * h + ca) ^ (m & 7)) * 16));
            }
#pragma unroll
            for (int u = 0; u < 4; u++) {
                int n = wn + 16 * u + rb;
                ldsm4(bf[2 * u][0], bf[2 * u][1], bf[2 * u + 1][0], bf[2 * u + 1][1],
                      ab + 16384 + n * 128 + (((2 * h + cb) ^ (n & 7)) * 16));
            }
#pragma unroll
            for (int im = 0; im < 4; im++)
#pragma unroll
                for (int jn = 0; jn < 8; jn++)
                    mma16816(acc[im][jn], a[im][0], a[im][1], a[im][2], a[im][3],
                             bf[jn][0], bf[jn][1]);
        }
        int pf = c + 2;
        if (pf < nchunk) {
            uint32_t ab2 = sbase + (pf % 3) * STG4;
#pragma unroll
            for (int l = 0; l < 8; l++) cp16(ab2 + swo[l], ag[l] + pf * 64);
#pragma unroll
            for (int l = 0; l < 8; l++) cp16(ab2 + 16384 + swo[l], wg[l] + pf * 64);
        }
        cp_commit();
    }

    const bool do_ln = LNQK && (bn + wn) < 2 * DIM;   // q or k region
    const float fin = (LNQK && (bn + wn) < DIM) ? QS : 1.f;

#pragma unroll
    for (int im = 0; im < 4; im++) {
        int r0 = bm + wm + 16 * im + g;
#pragma unroll
        for (int jn = 0; jn < 8; jn++) {
            int c0 = bn + wn + 8 * jn + 2 * tg;
            float bx = bias[c0], by = bias[c0 + 1];
            acc[im][jn][0] += bx; acc[im][jn][1] += by;
            acc[im][jn][2] += bx; acc[im][jn][3] += by;
        }
        if (do_ln) {
            float s0 = 0.f, ss0 = 0.f, s1 = 0.f, ss1 = 0.f;
#pragma unroll
            for (int jn = 0; jn < 8; jn++) {
                float v0 = acc[im][jn][0], v1 = acc[im][jn][1];
                float v2 = acc[im][jn][2], v3 = acc[im][jn][3];
                s0 += v0 + v1; ss0 += v0 * v0 + v1 * v1;
                s1 += v2 + v3; ss1 += v2 * v2 + v3 * v3;
            }
            s0  += __shfl_xor_sync(0xffffffffu, s0, 1);
            s0  += __shfl_xor_sync(0xffffffffu, s0, 2);
            ss0 += __shfl_xor_sync(0xffffffffu, ss0, 1);
            ss0 += __shfl_xor_sync(0xffffffffu, ss0, 2);
            s1  += __shfl_xor_sync(0xffffffffu, s1, 1);
            s1  += __shfl_xor_sync(0xffffffffu, s1, 2);
            ss1 += __shfl_xor_sync(0xffffffffu, ss1, 1);
            ss1 += __shfl_xor_sync(0xffffffffu, ss1, 2);
            float mu0 = s0 * (1.f / 64.f);
            float mu1 = s1 * (1.f / 64.f);
            float rs0 = rsqrtf(ss0 * (1.f / 64.f) - mu0 * mu0 + 1e-5f);
            float rs1 = rsqrtf(ss1 * (1.f / 64.f) - mu1 * mu1 + 1e-5f);
#pragma unroll
            for (int jn = 0; jn < 8; jn++) {
                int cs = 8 * jn + 2 * tg;
                float ga = gamma[cs], gb = gamma[cs + 1];
                float ba = beta[cs],  bb = beta[cs + 1];
                acc[im][jn][0] = ((acc[im][jn][0] - mu0) * rs0 * ga + ba) * fin;
                acc[im][jn][1] = ((acc[im][jn][1] - mu0) * rs0 * gb + bb) * fin;
                acc[im][jn][2] = ((acc[im][jn][2] - mu1) * rs1 * ga + ba) * fin;
                acc[im][jn][3] = ((acc[im][jn][3] - mu1) * rs1 * gb + bb) * fin;
            }
        }
#pragma unroll
        for (int jn = 0; jn < 8; jn++) {
            int c0 = bn + wn + 8 * jn + 2 * tg;
            if (HALF_OUT) {
                __half* C = (__half*)Cout;
                *(uint32_t*)(C + (size_t)r0 * N + c0) =
                    packh2(acc[im][jn][0], acc[im][jn][1]);
                *(uint32_t*)(C + (size_t)(r0 + 8) * N + c0) =
                    packh2(acc[im][jn][2], acc[im][jn][3]);
            } else {
                float* C = (float*)Cout;
                *(float2*)(C + (size_t)r0 * N + c0) =
                    make_float2(acc[im][jn][0], acc[im][jn][1]);
                *(float2*)(C + (size_t)(r0 + 8) * N + c0) =
                    make_float2(acc[im][jn][2], acc[im][jn][3]);
            }
        }
    }
}

// ---------------------------------------------------------------------------
// Flash attention, unnormalized softmax (P = 2^S; LN bounds |S|<=11.6 so
// 2^S fits fp16; normalization cancels the missing max-shift).
// BM=128 (4 warps x 32 rows), BN=64, hd=64. Triple-buffered K/V cp.async,
// ONE __syncthreads per iteration. Row sums via all-ones MMA.
// ---------------------------------------------------------------------------
__global__ __launch_bounds__(128, 2) void attn3(
    const __half* __restrict__ qkv, __half* __restrict__ out)
{
    __shared__ __align__(16) unsigned char sm[3 * 16384];   // 48KB

    const int q0 = blockIdx.x * 128;
    const int bh = blockIdx.y;
    const int b = bh / NHEAD, h = bh % NHEAD;
    const int t = threadIdx.x, lane = t & 31, warp = t >> 5;
    const int g = lane >> 2, tg = lane & 3;
    const int ra = (lane & 7) + 8 * ((lane >> 3) & 1), ca = lane >> 4;
    const int rb = (lane & 7) + 8 * (lane >> 4),       cb = (lane >> 3) & 1;
    const uint32_t sbase = smem_u32(sm);

    const __half* kvg = qkv + ((size_t)b * SEQ) * QKV_N + DIM + h * HD;
    int lrow[4], lch[4];
    uint32_t loff[4];
#pragma unroll
    for (int l = 0; l < 4; l++) {
        int s = t + l * 128;
        lrow[l] = s >> 3; lch[l] = s & 7;
        loff[l] = (uint32_t)(lrow[l] * 128 + ((lch[l] ^ (lrow[l] & 7)) * 16));
    }

    // ---- Stage Q into buf2; prefetch KV0 into buf0 concurrently ----
    {
        const __half* qg = qkv + ((size_t)(b * SEQ + q0)) * QKV_N + h * HD;
        uint32_t qb = sbase + 2 * 16384;
#pragma unroll
        for (int l = 0; l < 8; l++) {
            int s = t + l * 128, r = s >> 3, ch = s & 7;
            cp16(qb + r * 128 + ((ch ^ (r & 7)) * 16),
                 qg + (size_t)r * QKV_N + ch * 8);
        }
        cp_commit();
#pragma unroll
        for (int l = 0; l < 4; l++) {
            const __half* kg = kvg + (size_t)lrow[l] * QKV_N + lch[l] * 8;
            cp16(sbase + loff[l], kg);
            cp16(sbase + 8192 + loff[l], kg + DIM);
        }
        cp_commit();
        cp_wait<1>();   // Q ready (KV0 may still be in flight)
        __syncthreads();
    }
    uint32_t Qa[2][4][4];
    {
        uint32_t qb = sbase + 2 * 16384;
#pragma unroll
        for (int mi = 0; mi < 2; mi++) {
            int m = warp * 32 + mi * 16 + ra;
#pragma unroll
            for (int kd = 0; kd < 4; kd++)
                ldsm4(Qa[mi][kd][0], Qa[mi][kd][1], Qa[mi][kd][2], Qa[mi][kd][3],
                      qb + m * 128 + (((2 * kd + ca) ^ (m & 7)) * 16));
        }
    }
    __syncthreads();   // buf2 free for KV reuse

    float Oacc[2][8][4];
#pragma unroll
    for (int mi = 0; mi < 2; mi++)
#pragma unroll
        for (int dn = 0; dn < 8; dn++)
#pragma unroll
            for (int c = 0; c < 4; c++) Oacc[mi][dn][c] = 0.f;
    float Lacc[2][4];
#pragma unroll
    for (int mi = 0; mi < 2; mi++)
#pragma unroll
        for (int c = 0; c < 4; c++) Lacc[mi][c] = 0.f;

    const int NIT = SEQ / 64;   // 16
    for (int it = 0; it < NIT; it++) {
        if (it + 1 < NIT) {
            uint32_t bb = sbase + ((it + 1) % 3) * 16384;
            const __half* kg0 = kvg + (size_t)(it + 1) * 64 * QKV_N;
#pragma unroll
            for (int l = 0; l < 4; l++) {
                const __half* kg = kg0 + (size_t)lrow[l] * QKV_N + lch[l] * 8;
                cp16(bb + loff[l], kg);
                cp16(bb + 8192 + loff[l], kg + DIM);
            }
        }
        cp_commit();
        cp_wait<1>();
        __syncthreads();
        const uint32_t kb = sbase + (it % 3) * 16384;
        const uint32_t vb = kb + 8192;

        // S = Q @ K^T (log2 units; QS folded into q)
        float S[2][8][4];
#pragma unroll
        for (int mi = 0; mi < 2; mi++)
#pragma unroll
            for (int jn = 0; jn < 8; jn++)
#pragma unroll
                for (int c = 0; c < 4; c++) S[mi][jn][c] = 0.f;
#pragma unroll
        for (int kd = 0; kd < 4; kd++) {
#pragma unroll
            for (int u = 0; u < 4; u++) {
                int n = 16 * u + rb;
                uint32_t b0a, b1a, b0b, b1b;
                ldsm4(b0a, b1a, b0b, b1b,
                      kb + n * 128 + (((2 * kd + cb) ^ (n & 7)) * 16));
#pragma unroll
                for (int mi = 0; mi < 2; mi++) {
                    mma16816(S[mi][2 * u],     Qa[mi][kd][0], Qa[mi][kd][1],
                             Qa[mi][kd][2], Qa[mi][kd][3], b0a, b1a);
                    mma16816(S[mi][2 * u + 1], Qa[mi][kd][0], Qa[mi][kd][1],
                             Qa[mi][kd][2], Qa[mi][kd][3], b0b, b1b);
                }
            }
        }

        // P = 2^S in fp16 (pack, then one MUFU per 2 values)
        uint32_t Pa[2][4][4];
#pragma unroll
        for (int mi = 0; mi < 2; mi++) {
#pragma unroll
            for (int kt = 0; kt < 4; kt++) {
                Pa[mi][kt][0] = ex2x2(packh2(S[mi][2 * kt][0],     S[mi][2 * kt][1]));
                Pa[mi][kt][1] = ex2x2(packh2(S[mi][2 * kt][2],     S[mi][2 * kt][3]));
                Pa[mi][kt][2] = ex2x2(packh2(S[mi][2 * kt + 1][0], S[mi][2 * kt + 1][1]));
                Pa[mi][kt][3] = ex2x2(packh2(S[mi][2 * kt + 1][2], S[mi][2 * kt + 1][3]));
            }
#pragma unroll
            for (int kt = 0; kt < 4; kt++)
                mma16816(Lacc[mi], Pa[mi][kt][0], Pa[mi][kt][1],
                         Pa[mi][kt][2], Pa[mi][kt][3], ONESH2, ONESH2);
        }

        // O += P @ V
#pragma unroll
        for (int kt = 0; kt < 4; kt++) {
            int j = 16 * kt + ra;
#pragma unroll
            for (int dp = 0; dp < 4; dp++) {
                uint32_t b0a, b1a, b0b, b1b;
                ldsm4t(b0a, b1a, b0b, b1b,
                       vb + j * 128 + (((2 * dp + ca) ^ (j & 7)) * 16));
#pragma unroll
                for (int mi = 0; mi < 2; mi++) {
                    mma16816(Oacc[mi][2 * dp],     Pa[mi][kt][0], Pa[mi][kt][1],
                             Pa[mi][kt][2], Pa[mi][kt][3], b0a, b1a);
                    mma16816(Oacc[mi][2 * dp + 1], Pa[mi][kt][0], Pa[mi][kt][1],
                             Pa[mi][kt][2], Pa[mi][kt][3], b0b, b1b);
                }
            }
        }
    }

    // Normalize + store
#pragma unroll
    for (int mi = 0; mi < 2; mi++) {
        float inv0 = 1.f / Lacc[mi][0], inv1 = 1.f / Lacc[mi][2];
        int r0 = q0 + warp * 32 + mi * 16 + g;
        __half* o0 = out + ((size_t)b * SEQ + r0) * DIM + h * HD;
        __half* o1 = o0 + 8 * DIM;
#pragma unroll
        for (int dn = 0; dn < 8; dn++) {
            int c0 = 8 * dn + 2 * tg;
            *(uint32_t*)(o0 + c0) = packh2(Oacc[mi][dn][0] * inv0,
                                           Oacc[mi][dn][1] * inv0);
            *(uint32_t*)(o1 + c0) = packh2(Oacc[mi][dn][2] * inv1,
                                           Oacc[mi][dn][3] * inv1);
        }
    }
}

// ---------------------------------------------------------------------------
extern "C" void kernel_launch(void* const* d_in, const int* in_sizes, int n_in,
                              void* d_out, int out_size)
{
    const float* x      = (const float*)d_in[0];
    const float* qkv_w  = (const float*)d_in[1];
    const float* qkv_b  = (const float*)d_in[2];
    const float* proj_w = (const float*)d_in[3];
    const float* proj_b = (const float*)d_in[4];
    const float* qn_g   = (const float*)d_in[5];
    const float* qn_b   = (const float*)d_in[6];
    float* out = (float*)d_out;

    __half *xH, *wqH, *wpH, *qkvH, *attnH;
    cudaGetSymbolAddress((void**)&xH,    g_xH);
    cudaGetSymbolAddress((void**)&wqH,   g_wqH);
    cudaGetSymbolAddress((void**)&wpH,   g_wpH);
    cudaGetSymbolAddress((void**)&qkvH,  g_qkvH);
    cudaGetSymbolAddress((void**)&attnH, g_attnH);

    const int dyn = 3 * STG4;   // 98304
    cudaFuncSetAttribute(hgemm4<true, true>,
                         cudaFuncAttributeMaxDynamicSharedMemorySize, dyn);
    cudaFuncSetAttribute(hgemm4<false, false>,
                         cudaFuncAttributeMaxDynamicSharedMemorySize, dyn);

    // 0) all fp32 -> fp16 conversions in one launch
    cvt_all<<<(CV3 + 255) / 256, 256>>>(x, qkv_w, proj_w, xH, wqH, wpH);

    // 1) QKV projection + fused LayerNorm(q,k) + q-scale (fp16 out)
    hgemm4<true, true><<<dim3(QKV_N / 128, TOKENS / 128), 128, dyn>>>(
        xH, wqH, qkv_b, qkvH, qn_g, qn_b, TOKENS, QKV_N, DIM);

    // 2) Attention, unnormalized-exponent softmax (fp16 out)
    attn3<<<dim3(SEQ / 128, BATCH * NHEAD), 128>>>(qkvH, attnH);

    // 3) Output projection (fp32 out)
    hgemm4<false, false><<<dim3(DIM / 128, TOKENS / 128), 128, dyn>>>(
        attnH, wpH, proj_b, out, nullptr, nullptr, TOKENS, DIM, DIM);
}

// round 11
// speedup vs baseline: 1.0900x; 1.0158x over previous
#include <cuda_runtime.h>
#include <cuda_fp16.h>
#include <stdint.h>

#define DIM 768
#define NHEAD 12
#define HD 64
#define BATCH 8
#define SEQ 1024
#define TOKENS (BATCH*SEQ)   // 8192
#define QKV_N (3*DIM)        // 2304

// log2e * headdim^-0.5 folded into q at QKV epilogue -> S is in log2 units.
#define QS   (0.125f * 1.4426950408889634f)
#define ONESH2 0x3C003C00u   // half2(1.0, 1.0)

// Scratch (no allocation allowed)
__device__ __half g_xH  [TOKENS * DIM];
__device__ __half g_wqH [QKV_N * DIM];
__device__ __half g_wpH [DIM * DIM];
__device__ __half g_qkvH[TOKENS * QKV_N];
__device__ __half g_attnH[TOKENS * DIM];

__device__ __forceinline__ uint32_t smem_u32(const void* p) {
    return (uint32_t)__cvta_generic_to_shared(p);
}
__device__ __forceinline__ uint32_t packh2(float x, float y) {
    __half2 h = __floats2half2_rn(x, y);
    return *reinterpret_cast<uint32_t*>(&h);
}
__device__ __forceinline__ uint32_t ex2x2(uint32_t x) {
    uint32_t r;
    asm("ex2.approx.f16x2 %0, %1;\n" : "=r"(r) : "r"(x));
    return r;
}
__device__ __forceinline__ void ldsm4(uint32_t& r0, uint32_t& r1, uint32_t& r2,
                                      uint32_t& r3, uint32_t a) {
    asm volatile("ldmatrix.sync.aligned.m8n8.x4.shared.b16 {%0,%1,%2,%3},[%4];"
                 : "=r"(r0), "=r"(r1), "=r"(r2), "=r"(r3) : "r"(a));
}
__device__ __forceinline__ void ldsm4t(uint32_t& r0, uint32_t& r1, uint32_t& r2,
                                       uint32_t& r3, uint32_t a) {
    asm volatile("ldmatrix.sync.aligned.m8n8.x4.trans.shared.b16 {%0,%1,%2,%3},[%4];"
                 : "=r"(r0), "=r"(r1), "=r"(r2), "=r"(r3) : "r"(a));
}
__device__ __forceinline__ void mma16816(float c[4],
    uint32_t a0, uint32_t a1, uint32_t a2, uint32_t a3, uint32_t b0, uint32_t b1)
{
    asm volatile(
        "mma.sync.aligned.m16n8k16.row.col.f32.f16.f16.f32 "
        "{%0,%1,%2,%3},{%4,%5,%6,%7},{%8,%9},{%0,%1,%2,%3};"
        : "+f"(c[0]), "+f"(c[1]), "+f"(c[2]), "+f"(c[3])
        : "r"(a0), "r"(a1), "r"(a2), "r"(a3), "r"(b0), "r"(b1));
}
__device__ __forceinline__ void cp16(uint32_t dst, const void* src) {
    asm volatile("cp.async.cg.shared.global [%0], [%1], 16;\n" :: "r"(dst), "l"(src));
}
__device__ __forceinline__ void cp_commit() {
    asm volatile("cp.async.commit_group;\n" ::: "memory");
}
template<int N> __device__ __forceinline__ void cp_wait() {
    asm volatile("cp.async.wait_group %0;\n" :: "n"(N) : "memory");
}

// ---------------------------------------------------------------------------
// fused fp32 -> fp16 conversion of x, qkv_w, proj_w in one launch
// ---------------------------------------------------------------------------
#define CV1 (TOKENS * DIM / 8)
#define CV2 (CV1 + QKV_N * DIM / 8)
#define CV3 (CV2 + DIM * DIM / 8)
__global__ __launch_bounds__(256) void cvt_all(
    const float* __restrict__ x, const float* __restrict__ wq,
    const float* __restrict__ wp, __half* __restrict__ xH,
    __half* __restrict__ wqH, __half* __restrict__ wpH)
{
    int i = blockIdx.x * 256 + threadIdx.x;
    const float* in;
    __half* out;
    int j;
    if (i < CV1)      { in = x;  out = xH;  j = i; }
    else if (i < CV2) { in = wq; out = wqH; j = i - CV1; }
    else if (i < CV3) { in = wp; out = wpH; j = i - CV2; }
    else return;
    float4 a = ((const float4*)in)[2 * j];
    float4 b = ((const float4*)in)[2 * j + 1];
    uint4 o;
    o.x = packh2(a.x, a.y); o.y = packh2(a.z, a.w);
    o.z = packh2(b.x, b.y); o.w = packh2(b.z, b.w);
    ((uint4*)out)[j] = o;
}

// ---------------------------------------------------------------------------
// QKV GEMM (unchanged R10 winner): 128x128 block, 4 warps (2x2 of 64x64),
// BK=64, 3-stage cp.async, dynamic smem 96KB, 2 CTAs/SM.
// LNQK: fused per-head(64) LayerNorm for q,k regions; q scaled by QS.
// ---------------------------------------------------------------------------
#define STG4 32768
template<bool HALF_OUT, bool LNQK>
__global__ __launch_bounds__(128, 2) void hgemm4(
    const __half* __restrict__ A, const __half* __restrict__ W,
    const float* __restrict__ bias, void* __restrict__ Cout,
    const float* __restrict__ gamma, const float* __restrict__ beta,
    int M, int N, int K)
{
    extern __shared__ __align__(16) unsigned char sm4[];

    const int bm = blockIdx.y * 128, bn = blockIdx.x * 128;
    const int t = threadIdx.x, lane = t & 31, warp = t >> 5;
    const int wm = (warp & 1) * 64, wn = (warp >> 1) * 64;
    const int g = lane >> 2, tg = lane & 3;
    const int ra = (lane & 7) + 8 * ((lane >> 3) & 1), ca = lane >> 4;
    const int rb = (lane & 7) + 8 * (lane >> 4),       cb = (lane >> 3) & 1;
    const uint32_t sbase = smem_u32(sm4);

    uint32_t swo[8];
    const __half* ag[8];
    const __half* wg[8];
#pragma unroll
    for (int l = 0; l < 8; l++) {
        int s = t + l * 128, r = s >> 3, ch = s & 7;
        swo[l] = (uint32_t)(r * 128 + ((ch ^ (r & 7)) * 16));
        ag[l] = A + (size_t)(bm + r) * K + ch * 8;
        wg[l] = W + (size_t)(bn + r) * K + ch * 8;
    }

    const int nchunk = K >> 6;
#pragma unroll
    for (int c = 0; c < 2; c++) {
        uint32_t ab = sbase + c * STG4;
#pragma unroll
        for (int l = 0; l < 8; l++) cp16(ab + swo[l], ag[l] + c * 64);
#pragma unroll
        for (int l = 0; l < 8; l++) cp16(ab + 16384 + swo[l], wg[l] + c * 64);
        cp_commit();
    }

    float acc[4][8][4];
#pragma unroll
    for (int i = 0; i < 4; i++)
#pragma unroll
        for (int j = 0; j < 8; j++)
#pragma unroll
            for (int c = 0; c < 4; c++) acc[i][j][c] = 0.f;

    for (int c = 0; c < nchunk; c++) {
        cp_wait<1>();
        __syncthreads();
        const uint32_t ab = sbase + (c % 3) * STG4;
#pragma unroll
        for (int h = 0; h < 4; h++) {
            uint32_t a[4][4], bf[8][2];
#pragma unroll
            for (int im = 0; im < 4; im++) {
                int m = wm + 16 * im + ra;
                ldsm4(a[im][0], a[im][1], a[im][2], a[im][3],
                      ab + m * 128 + (((2 * h + ca) ^ (m & 7)) * 16));
            }
#pragma unroll
            for (int u = 0; u < 4; u++) {
                int n = wn + 16 * u + rb;
                ldsm4(bf[2 * u][0], bf[2 * u][1], bf[2 * u + 1][0], bf[2 * u + 1][1],
                      ab + 16384 + n * 128 + (((2 * h + cb) ^ (n & 7)) * 16));
            }
#pragma unroll
            for (int im = 0; im < 4; im++)
#pragma unroll
                for (int jn = 0; jn < 8; jn++)
                    mma16816(acc[im][jn], a[im][0], a[im][1], a[im][2], a[im][3],
                             bf[jn][0], bf[jn][1]);
        }
        int pf = c + 2;
        if (pf < nchunk) {
            uint32_t ab2 = sbase + (pf % 3) * STG4;
#pragma unroll
            for (int l = 0; l < 8; l++) cp16(ab2 + swo[l], ag[l] + pf * 64);
#pragma unroll
            for (int l = 0; l < 8; l++) cp16(ab2 + 16384 + swo[l], wg[l] + pf * 64);
        }
        cp_commit();
    }

    const bool do_ln = LNQK && (bn + wn) < 2 * DIM;
    const float fin = (LNQK && (bn + wn) < DIM) ? QS : 1.f;

#pragma unroll
    for (int im = 0; im < 4; im++) {
        int r0 = bm + wm + 16 * im + g;
#pragma unroll
        for (int jn = 0; jn < 8; jn++) {
            int c0 = bn + wn + 8 * jn + 2 * tg;
            float bx = bias[c0], by = bias[c0 + 1];
            acc[im][jn][0] += bx; acc[im][jn][1] += by;
            acc[im][jn][2] += bx; acc[im][jn][3] += by;
        }
        if (do_ln) {
            float s0 = 0.f, ss0 = 0.f, s1 = 0.f, ss1 = 0.f;
#pragma unroll
            for (int jn = 0; jn < 8; jn++) {
                float v0 = acc[im][jn][0], v1 = acc[im][jn][1];
                float v2 = acc[im][jn][2], v3 = acc[im][jn][3];
                s0 += v0 + v1; ss0 += v0 * v0 + v1 * v1;
                s1 += v2 + v3; ss1 += v2 * v2 + v3 * v3;
            }
            s0  += __shfl_xor_sync(0xffffffffu, s0, 1);
            s0  += __shfl_xor_sync(0xffffffffu, s0, 2);
            ss0 += __shfl_xor_sync(0xffffffffu, ss0, 1);
            ss0 += __shfl_xor_sync(0xffffffffu, ss0, 2);
            s1  += __shfl_xor_sync(0xffffffffu, s1, 1);
            s1  += __shfl_xor_sync(0xffffffffu, s1, 2);
            ss1 += __shfl_xor_sync(0xffffffffu, ss1, 1);
            ss1 += __shfl_xor_sync(0xffffffffu, ss1, 2);
            float mu0 = s0 * (1.f / 64.f);
            float mu1 = s1 * (1.f / 64.f);
            float rs0 = rsqrtf(ss0 * (1.f / 64.f) - mu0 * mu0 + 1e-5f);
            float rs1 = rsqrtf(ss1 * (1.f / 64.f) - mu1 * mu1 + 1e-5f);
#pragma unroll
            for (int jn = 0; jn < 8; jn++) {
                int cs = 8 * jn + 2 * tg;
                float ga = gamma[cs], gb = gamma[cs + 1];
                float ba = beta[cs],  bb = beta[cs + 1];
                acc[im][jn][0] = ((acc[im][jn][0] - mu0) * rs0 * ga + ba) * fin;
                acc[im][jn][1] = ((acc[im][jn][1] - mu0) * rs0 * gb + bb) * fin;
                acc[im][jn][2] = ((acc[im][jn][2] - mu1) * rs1 * ga + ba) * fin;
                acc[im][jn][3] = ((acc[im][jn][3] - mu1) * rs1 * gb + bb) * fin;
            }
        }
#pragma unroll
        for (int jn = 0; jn < 8; jn++) {
            int c0 = bn + wn + 8 * jn + 2 * tg;
            if (HALF_OUT) {
                __half* C = (__half*)Cout;
                *(uint32_t*)(C + (size_t)r0 * N + c0) =
                    packh2(acc[im][jn][0], acc[im][jn][1]);
                *(uint32_t*)(C + (size_t)(r0 + 8) * N + c0) =
                    packh2(acc[im][jn][2], acc[im][jn][3]);
            } else {
                float* C = (float*)Cout;
                *(float2*)(C + (size_t)r0 * N + c0) =
                    make_float2(acc[im][jn][0], acc[im][jn][1]);
                *(float2*)(C + (size_t)(r0 + 8) * N + c0) =
                    make_float2(acc[im][jn][2], acc[im][jn][3]);
            }
        }
    }
}

// ---------------------------------------------------------------------------
// proj GEMM: 64x128 block, 4 warps (2x2 of 32x64), BK=64, 3-stage cp.async,
// 24KB stages (72KB dynamic), 3 CTAs/SM -> less wave quantization (768 CTAs).
// fp32 out + bias.
// ---------------------------------------------------------------------------
#define STG5 24576   // A 64x128B (8KB) + B 128x128B (16KB)
__global__ __launch_bounds__(128, 3) void hgemm5(
    const __half* __restrict__ A, const __half* __restrict__ W,
    const float* __restrict__ bias, float* __restrict__ C,
    int M, int N, int K)
{
    extern __shared__ __align__(16) unsigned char sm5[];

    const int bm = blockIdx.y * 64, bn = blockIdx.x * 128;
    const int t = threadIdx.x, lane = t & 31, warp = t >> 5;
    const int wm = (warp & 1) * 32, wn = (warp >> 1) * 64;
    const int g = lane >> 2, tg = lane & 3;
    const int ra = (lane & 7) + 8 * ((lane >> 3) & 1), ca = lane >> 4;
    const int rb = (lane & 7) + 8 * (lane >> 4),       cb = (lane >> 3) & 1;
    const uint32_t sbase = smem_u32(sm5);

    // A: 64 rows x 8 chunks = 512 -> 4/thread; B: 1024 -> 8/thread
    uint32_t aswo[4], wswo[8];
    const __half* ag[4];
    const __half* wg[8];
#pragma unroll
    for (int l = 0; l < 4; l++) {
        int s = t + l * 128, r = s >> 3, ch = s & 7;
        aswo[l] = (uint32_t)(r * 128 + ((ch ^ (r & 7)) * 16));
        ag[l] = A + (size_t)(bm + r) * K + ch * 8;
    }
#pragma unroll
    for (int l = 0; l < 8; l++) {
        int s = t + l * 128, r = s >> 3, ch = s & 7;
        wswo[l] = (uint32_t)(8192 + r * 128 + ((ch ^ (r & 7)) * 16));
        wg[l] = W + (size_t)(bn + r) * K + ch * 8;
    }

    const int nchunk = K >> 6;
#pragma unroll
    for (int c = 0; c < 2; c++) {
        uint32_t ab = sbase + c * STG5;
#pragma unroll
        for (int l = 0; l < 4; l++) cp16(ab + aswo[l], ag[l] + c * 64);
#pragma unroll
        for (int l = 0; l < 8; l++) cp16(ab + wswo[l], wg[l] + c * 64);
        cp_commit();
    }

    float acc[2][8][4];
#pragma unroll
    for (int i = 0; i < 2; i++)
#pragma unroll
        for (int j = 0; j < 8; j++)
#pragma unroll
            for (int c = 0; c < 4; c++) acc[i][j][c] = 0.f;

    for (int c = 0; c < nchunk; c++) {
        cp_wait<1>();
        __syncthreads();
        const uint32_t ab = sbase + (c % 3) * STG5;
#pragma unroll
        for (int h = 0; h < 4; h++) {
            uint32_t a[2][4], bf[8][2];
#pragma unroll
            for (int im = 0; im < 2; im++) {
                int m = wm + 16 * im + ra;
                ldsm4(a[im][0], a[im][1], a[im][2], a[im][3],
                      ab + m * 128 + (((2 * h + ca) ^ (m & 7)) * 16));
            }
#pragma unroll
            for (int u = 0; u < 4; u++) {
                int n = wn + 16 * u + rb;
                ldsm4(bf[2 * u][0], bf[2 * u][1], bf[2 * u + 1][0], bf[2 * u + 1][1],
                      ab + 8192 + n * 128 + (((2 * h + cb) ^ (n & 7)) * 16));
            }
#pragma unroll
            for (int im = 0; im < 2; im++)
#pragma unroll
                for (int jn = 0; jn < 8; jn++)
                    mma16816(acc[im][jn], a[im][0], a[im][1], a[im][2], a[im][3],
                             bf[jn][0], bf[jn][1]);
        }
        int pf = c + 2;
        if (pf < nchunk) {
            uint32_t ab2 = sbase + (pf % 3) * STG5;
#pragma unroll
            for (int l = 0; l < 4; l++) cp16(ab2 + aswo[l], ag[l] + pf * 64);
#pragma unroll
            for (int l = 0; l < 8; l++) cp16(ab2 + wswo[l], wg[l] + pf * 64);
        }
        cp_commit();
    }

#pragma unroll
    for (int im = 0; im < 2; im++) {
        int r0 = bm + wm + 16 * im + g;
#pragma unroll
        for (int jn = 0; jn < 8; jn++) {
            int c0 = bn + wn + 8 * jn + 2 * tg;
            float bx = bias[c0], by = bias[c0 + 1];
            *(float2*)(C + (size_t)r0 * N + c0) =
                make_float2(acc[im][jn][0] + bx, acc[im][jn][1] + by);
            *(float2*)(C + (size_t)(r0 + 8) * N + c0) =
                make_float2(acc[im][jn][2] + bx, acc[im][jn][3] + by);
        }
    }
}

// ---------------------------------------------------------------------------
// Flash attention v4: per-mi fused pipeline (QK -> ex2 -> PV per m-tile)
// drops peak register pressure -> 3 CTAs/SM. K/V ldsm done twice (once per
// m-tile) — ldsm stays non-binding vs 136 HMMA/iter. Unnormalized softmax
// (P = 2^S), row sums via all-ones MMA. Triple-buffered K/V, one barrier/iter.
// ---------------------------------------------------------------------------
__global__ __launch_bounds__(128, 3) void attn4(
    const __half* __restrict__ qkv, __half* __restrict__ out)
{
    __shared__ __align__(16) unsigned char sm[3 * 16384];   // 48KB

    const int q0 = blockIdx.x * 128;
    const int bh = blockIdx.y;
    const int b = bh / NHEAD, h = bh % NHEAD;
    const int t = threadIdx.x, lane = t & 31, warp = t >> 5;
    const int g = lane >> 2, tg = lane & 3;
    const int ra = (lane & 7) + 8 * ((lane >> 3) & 1), ca = lane >> 4;
    const int rb = (lane & 7) + 8 * (lane >> 4),       cb = (lane >> 3) & 1;
    const uint32_t sbase = smem_u32(sm);

    const __half* kvg = qkv + ((size_t)b * SEQ) * QKV_N + DIM + h * HD;
    int lrow[4], lch[4];
    uint32_t loff[4];
#pragma unroll
    for (int l = 0; l < 4; l++) {
        int s = t + l * 128;
        lrow[l] = s >> 3; lch[l] = s & 7;
        loff[l] = (uint32_t)(lrow[l] * 128 + ((lch[l] ^ (lrow[l] & 7)) * 16));
    }

    // ---- Stage Q into buf2; prefetch KV0 into buf0 concurrently ----
    {
        const __half* qg = qkv + ((size_t)(b * SEQ + q0)) * QKV_N + h * HD;
        uint32_t qb = sbase + 2 * 16384;
#pragma unroll
        for (int l = 0; l < 8; l++) {
            int s = t + l * 128, r = s >> 3, ch = s & 7;
            cp16(qb + r * 128 + ((ch ^ (r & 7)) * 16),
                 qg + (size_t)r * QKV_N + ch * 8);
        }
        cp_commit();
#pragma unroll
        for (int l = 0; l < 4; l++) {
            const __half* kg = kvg + (size_t)lrow[l] * QKV_N + lch[l] * 8;
            cp16(sbase + loff[l], kg);
            cp16(sbase + 8192 + loff[l], kg + DIM);
        }
        cp_commit();
        cp_wait<1>();   // Q ready
        __syncthreads();
    }
    uint32_t Qa[2][4][4];
    {
        uint32_t qb = sbase + 2 * 16384;
#pragma unroll
        for (int mi = 0; mi < 2; mi++) {
            int m = warp * 32 + mi * 16 + ra;
#pragma unroll
            for (int kd = 0; kd < 4; kd++)
                ldsm4(Qa[mi][kd][0], Qa[mi][kd][1], Qa[mi][kd][2], Qa[mi][kd][3],
                      qb + m * 128 + (((2 * kd + ca) ^ (m & 7)) * 16));
        }
    }
    __syncthreads();   // buf2 free for KV reuse

    float Oacc[2][8][4];
#pragma unroll
    for (int mi = 0; mi < 2; mi++)
#pragma unroll
        for (int dn = 0; dn < 8; dn++)
#pragma unroll
            for (int c = 0; c < 4; c++) Oacc[mi][dn][c] = 0.f;
    float Lacc[2][4];
#pragma unroll
    for (int mi = 0; mi < 2; mi++)
#pragma unroll
        for (int c = 0; c < 4; c++) Lacc[mi][c] = 0.f;

    const int NIT = SEQ / 64;   // 16
    for (int it = 0; it < NIT; it++) {
        if (it + 1 < NIT) {
            uint32_t bb = sbase + ((it + 1) % 3) * 16384;
            const __half* kg0 = kvg + (size_t)(it + 1) * 64 * QKV_N;
#pragma unroll
            for (int l = 0; l < 4; l++) {
                const __half* kg = kg0 + (size_t)lrow[l] * QKV_N + lch[l] * 8;
                cp16(bb + loff[l], kg);
                cp16(bb + 8192 + loff[l], kg + DIM);
            }
        }
        cp_commit();
        cp_wait<1>();
        __syncthreads();
        const uint32_t kb = sbase + (it % 3) * 16384;
        const uint32_t vb = kb + 8192;

        // Per-m-tile fused pipeline: keeps only one S[8][4] live at a time.
#pragma unroll
        for (int mi = 0; mi < 2; mi++) {
            // S = Q @ K^T (log2 units)
            float S[8][4];
#pragma unroll
            for (int jn = 0; jn < 8; jn++)
#pragma unroll
                for (int c = 0; c < 4; c++) S[jn][c] = 0.f;
#pragma unroll
            for (int kd = 0; kd < 4; kd++) {
#pragma unroll
                for (int u = 0; u < 4; u++) {
                    int n = 16 * u + rb;
                    uint32_t b0a, b1a, b0b, b1b;
                    ldsm4(b0a, b1a, b0b, b1b,
                          kb + n * 128 + (((2 * kd + cb) ^ (n & 7)) * 16));
                    mma16816(S[2 * u],     Qa[mi][kd][0], Qa[mi][kd][1],
                             Qa[mi][kd][2], Qa[mi][kd][3], b0a, b1a);
                    mma16816(S[2 * u + 1], Qa[mi][kd][0], Qa[mi][kd][1],
                             Qa[mi][kd][2], Qa[mi][kd][3], b0b, b1b);
                }
            }

            // P = 2^S in fp16
            uint32_t Pa[4][4];
#pragma unroll
            for (int kt = 0; kt < 4; kt++) {
                Pa[kt][0] = ex2x2(packh2(S[2 * kt][0],     S[2 * kt][1]));
                Pa[kt][1] = ex2x2(packh2(S[2 * kt][2],     S[2 * kt][3]));
                Pa[kt][2] = ex2x2(packh2(S[2 * kt + 1][0], S[2 * kt + 1][1]));
                Pa[kt][3] = ex2x2(packh2(S[2 * kt + 1][2], S[2 * kt + 1][3]));
            }
#pragma unroll
            for (int kt = 0; kt < 4; kt++)
                mma16816(Lacc[mi], Pa[kt][0], Pa[kt][1], Pa[kt][2], Pa[kt][3],
                         ONESH2, ONESH2);

            // O += P @ V
#pragma unroll
            for (int kt = 0; kt < 4; kt++) {
                int j = 16 * kt + ra;
#pragma unroll
                for (int dp = 0; dp < 4; dp++) {
                    uint32_t b0a, b1a, b0b, b1b;
                    ldsm4t(b0a, b1a, b0b, b1b,
                           vb + j * 128 + (((2 * dp + ca) ^ (j & 7)) * 16));
                    mma16816(Oacc[mi][2 * dp],     Pa[kt][0], Pa[kt][1],
                             Pa[kt][2], Pa[kt][3], b0a, b1a);
                    mma16816(Oacc[mi][2 * dp + 1], Pa[kt][0], Pa[kt][1],
                             Pa[kt][2], Pa[kt][3], b0b, b1b);
                }
            }
        }
    }

    // Normalize + store
#pragma unroll
    for (int mi = 0; mi < 2; mi++) {
        float inv0 = 1.f / Lacc[mi][0], inv1 = 1.f / Lacc[mi][2];
        int r0 = q0 + warp * 32 + mi * 16 + g;
        __half* o0 = out + ((size_t)b * SEQ + r0) * DIM + h * HD;
        __half* o1 = o0 + 8 * DIM;
#pragma unroll
        for (int dn = 0; dn < 8; dn++) {
            int c0 = 8 * dn + 2 * tg;
            *(uint32_t*)(o0 + c0) = packh2(Oacc[mi][dn][0] * inv0,
                                           Oacc[mi][dn][1] * inv0);
            *(uint32_t*)(o1 + c0) = packh2(Oacc[mi][dn][2] * inv1,
                                           Oacc[mi][dn][3] * inv1);
        }
    }
}

// ---------------------------------------------------------------------------
extern "C" void kernel_launch(void* const* d_in, const int* in_sizes, int n_in,
                              void* d_out, int out_size)
{
    const float* x      = (const float*)d_in[0];
    const float* qkv_w  = (const float*)d_in[1];
    const float* qkv_b  = (const float*)d_in[2];
    const float* proj_w = (const float*)d_in[3];
    const float* proj_b = (const float*)d_in[4];
    const float* qn_g   = (const float*)d_in[5];
    const float* qn_b   = (const float*)d_in[6];
    float* out = (float*)d_out;

    __half *xH, *wqH, *wpH, *qkvH, *attnH;
    cudaGetSymbolAddress((void**)&xH,    g_xH);
    cudaGetSymbolAddress((void**)&wqH,   g_wqH);
    cudaGetSymbolAddress((void**)&wpH,   g_wpH);
    cudaGetSymbolAddress((void**)&qkvH,  g_qkvH);
    cudaGetSymbolAddress((void**)&attnH, g_attnH);

    const int dyn4 = 3 * STG4;   // 98304
    const int dyn5 = 3 * STG5;   // 73728
    cudaFuncSetAttribute(hgemm4<true, true>,
                         cudaFuncAttributeMaxDynamicSharedMemorySize, dyn4);
    cudaFuncSetAttribute(hgemm5,
                         cudaFuncAttributeMaxDynamicSharedMemorySize, dyn5);

    // 0) all fp32 -> fp16 conversions in one launch
    cvt_all<<<(CV3 + 255) / 256, 256>>>(x, qkv_w, proj_w, xH, wqH, wpH);

    // 1) QKV projection + fused LayerNorm(q,k) + q-scale (fp16 out)
    hgemm4<true, true><<<dim3(QKV_N / 128, TOKENS / 128), 128, dyn4>>>(
        xH, wqH, qkv_b, qkvH, qn_g, qn_b, TOKENS, QKV_N, DIM);

    // 2) Attention, unnormalized-exponent softmax (fp16 out), 3 CTAs/SM
    attn4<<<dim3(SEQ / 128, BATCH * NHEAD), 128>>>(qkvH, attnH);

    // 3) Output projection (fp32 out), 64x128 tiles, 3 CTAs/SM
    hgemm5<<<dim3(DIM / 128, TOKENS / 64), 128, dyn5>>>(
        attnH, wpH, proj_b, out, TOKENS, DIM, DIM);
}